// round 7
// baseline (speedup 1.0000x reference)
#include <cuda_runtime.h>
#include <cuda_fp16.h>
#include <cstdint>

#define NB   32
#define LA   512
#define LB   512
#define DIM  768
#define OUTC 3072
#define NROW (NB*512)   // 16384 scalar slots

// ---------------- scratch (__device__ globals; no allocation allowed) -------
__device__ __align__(1024) __half g_ah [(size_t)NB*LA*DIM], g_al [(size_t)NB*LA*DIM];
__device__ __align__(1024) __half g_bh [(size_t)NB*LB*DIM], g_bl [(size_t)NB*LB*DIM];
__device__ __align__(1024) __half g_aTh[(size_t)NB*DIM*LA], g_aTl[(size_t)NB*DIM*LA];
__device__ __align__(1024) __half g_bTh[(size_t)NB*DIM*LB], g_bTl[(size_t)NB*DIM*LB];
__device__ __align__(1024) float g_e[(size_t)NB*LA*LB];
// partial stats: [4 blocks][NB*512]
__device__ float g_rpmax[4*NROW], g_rpsum[4*NROW];
__device__ float g_cpmax[4*NROW], g_cpsum[4*NROW];
// reduced scalars
__device__ float g_rowm[NROW], g_rowi[NROW], g_colm[NROW], g_coli[NROW];

// ---------------- low-level helpers (portable PTX only) ---------------------
__device__ __forceinline__ uint32_t smem_to_u32(const void* p) {
    uint32_t a;
    asm("{ .reg .u64 t; cvta.to.shared.u64 t, %1; cvt.u32.u64 %0, t; }" : "=r"(a) : "l"(p));
    return a;
}
__device__ __forceinline__ void cp16(uint32_t dst, const void* src) {
    asm volatile("cp.async.cg.shared.global [%0], [%1], 16;" :: "r"(dst), "l"(src));
}
__device__ __forceinline__ void cp_commit() { asm volatile("cp.async.commit_group;"); }
__device__ __forceinline__ void cp_wait1()  { asm volatile("cp.async.wait_group 1;"); }
__device__ __forceinline__ void cp_wait0()  { asm volatile("cp.async.wait_group 0;"); }

__device__ __forceinline__ void ldsm4(uint32_t* r, uint32_t addr) {
    asm volatile("ldmatrix.sync.aligned.m8n8.x4.shared.b16 {%0,%1,%2,%3}, [%4];"
                 : "=r"(r[0]), "=r"(r[1]), "=r"(r[2]), "=r"(r[3]) : "r"(addr));
}
// fp32 accumulator HMMA (half rate)
__device__ __forceinline__ void mma_f16(float* c, const uint32_t* a, const uint32_t* b) {
    asm volatile("mma.sync.aligned.m16n8k16.row.col.f32.f16.f16.f32 "
                 "{%0,%1,%2,%3}, {%4,%5,%6,%7}, {%8,%9}, {%0,%1,%2,%3};"
                 : "+f"(c[0]), "+f"(c[1]), "+f"(c[2]), "+f"(c[3])
                 : "r"(a[0]), "r"(a[1]), "r"(a[2]), "r"(a[3]), "r"(b[0]), "r"(b[1]));
}
// fp16 accumulator HMMA (full rate) — for low-order split passes
__device__ __forceinline__ void mma_f16acc(uint32_t* c, const uint32_t* a, const uint32_t* b) {
    asm volatile("mma.sync.aligned.m16n8k16.row.col.f16.f16.f16.f16 "
                 "{%0,%1}, {%2,%3,%4,%5}, {%6,%7}, {%0,%1};"
                 : "+r"(c[0]), "+r"(c[1])
                 : "r"(a[0]), "r"(a[1]), "r"(a[2]), "r"(a[3]), "r"(b[0]), "r"(b[1]));
}
// merge f16 partial accumulator into fp32 accumulator
__device__ __forceinline__ void merge_lo(float* acc, const uint32_t* lo) {
    float2 f0 = __half22float2(*(const __half2*)&lo[0]);
    float2 f1 = __half22float2(*(const __half2*)&lo[1]);
    acc[0] += f0.x; acc[1] += f0.y; acc[2] += f1.x; acc[3] += f1.y;
}

#define TILE_BYTES 8192            // 128 rows x 32 halfs (2 ks-halves of 16)

// swizzled smem byte offset inside a tile for (row, 16B-chunk kh)
__device__ __forceinline__ uint32_t sw_off(int row, int kh) {
    return (uint32_t)(row * 32 + ((kh ^ ((row >> 2) & 1)) << 4));
}

// =============================================================================
// GEMM1: e = (Ah+Al)(Bh+Bl)^T. hh pass -> f32 acc; hl+lh -> shared f16 acc.
// fp32 e store + row/col partial softmax stats.
// =============================================================================
#define G1_STAGE (4*TILE_BYTES)
#define G1_SCRATCH 8192
#define G1_SMEM (2*G1_STAGE + G1_SCRATCH + 1024)

__global__ __launch_bounds__(256)
void gemm1_k(const __half* __restrict__ Ah, const __half* __restrict__ Al,
             const __half* __restrict__ Bh, const __half* __restrict__ Bl,
             float* __restrict__ E)
{
    extern __shared__ char smraw[];
    uint32_t sm0 = smem_to_u32(smraw);
    uint32_t smb = (sm0 + 1023u) & ~1023u;
    char* smc = smraw + (smb - sm0);

    const int tid = threadIdx.x;
    const int lid = tid & 31, wid = tid >> 5;
    const int wm = wid >> 2, wn = wid & 3;
    const int g = lid >> 2, t = lid & 3;
    const int z = blockIdx.z, m0 = blockIdx.y * 128, n0 = blockIdx.x * 128;
    const int K = DIM;

    const __half* srcs[4] = {
        Ah + ((size_t)z * LA + m0) * K, Al + ((size_t)z * LA + m0) * K,
        Bh + ((size_t)z * LB + n0) * K, Bl + ((size_t)z * LB + n0) * K };

    const int ar  = (lid & 7) | (((lid >> 3) & 1) << 3);
    const int akh = lid >> 4;
    uint32_t aoff[4];
    #pragma unroll
    for (int i = 0; i < 4; i++)
        aoff[i] = sw_off(wm * 64 + i * 16 + ar, akh);
    const int br  = (lid & 7) | ((lid >> 4) << 3);
    const int bkh = (lid >> 3) & 1;
    uint32_t boff[2];
    #pragma unroll
    for (int j2 = 0; j2 < 2; j2++)
        boff[j2] = sw_off(wn * 32 + j2 * 16 + br, bkh);

    float acc[4][4][4];
    uint32_t alo[4][4][2];
    #pragma unroll
    for (int i = 0; i < 4; i++)
        #pragma unroll
        for (int j = 0; j < 4; j++) {
            #pragma unroll
            for (int r = 0; r < 4; r++) acc[i][j][r] = 0.f;
            alo[i][j][0] = 0u; alo[i][j][1] = 0u;
        }

    const int nk = K >> 5;

    auto issue_stage = [&](int s, int kt) {
        uint32_t sb = smb + s * G1_STAGE;
        #pragma unroll
        for (int tl = 0; tl < 4; tl++) {
            const __half* src = srcs[tl];
            uint32_t tb = sb + tl * TILE_BYTES;
            #pragma unroll
            for (int it = 0; it < 2; it++) {
                int idx = tid + it * 256;
                int m = idx >> 2, ks = (idx >> 1) & 1, kh = idx & 1;
                cp16(tb + ks * 4096 + sw_off(m, kh),
                     src + (size_t)m * K + kt * 32 + ks * 16 + kh * 8);
            }
        }
    };

    issue_stage(0, 0);
    cp_commit();

    for (int kt = 0; kt < nk; kt++) {
        if (kt + 1 < nk) { issue_stage((kt + 1) & 1, kt + 1); }
        cp_commit();
        cp_wait1();
        __syncthreads();

        uint32_t st = smb + (kt & 1) * G1_STAGE;
        #pragma unroll
        for (int ks = 0; ks < 2; ks++) {
            uint32_t a_h[4][4], a_l[4][4], b_h[4][2], b_l[4][2];
            #pragma unroll
            for (int i = 0; i < 4; i++) {
                ldsm4(a_h[i], st + 0 * TILE_BYTES + ks * 4096 + aoff[i]);
                ldsm4(a_l[i], st + 1 * TILE_BYTES + ks * 4096 + aoff[i]);
            }
            #pragma unroll
            for (int j2 = 0; j2 < 2; j2++) {
                uint32_t rh[4], rl[4];
                ldsm4(rh, st + 2 * TILE_BYTES + ks * 4096 + boff[j2]);
                ldsm4(rl, st + 3 * TILE_BYTES + ks * 4096 + boff[j2]);
                b_h[j2*2+0][0] = rh[0]; b_h[j2*2+0][1] = rh[1];
                b_h[j2*2+1][0] = rh[2]; b_h[j2*2+1][1] = rh[3];
                b_l[j2*2+0][0] = rl[0]; b_l[j2*2+0][1] = rl[1];
                b_l[j2*2+1][0] = rl[2]; b_l[j2*2+1][1] = rl[3];
            }
            #pragma unroll
            for (int i = 0; i < 4; i++)
                #pragma unroll
                for (int j = 0; j < 4; j++) {
                    mma_f16(acc[i][j], a_h[i], b_h[j]);          // hh: f32 acc
                    mma_f16acc(alo[i][j], a_h[i], b_l[j]);       // hl: f16 acc
                    mma_f16acc(alo[i][j], a_l[i], b_h[j]);       // lh: f16 acc
                }
        }
        __syncthreads();
    }

    // merge f16 partials into fp32 accumulators
    #pragma unroll
    for (int i = 0; i < 4; i++)
        #pragma unroll
        for (int j = 0; j < 4; j++)
            merge_lo(acc[i][j], alo[i][j]);

    // ---- store e (fp32) ----
    #pragma unroll
    for (int i = 0; i < 4; i++)
        #pragma unroll
        for (int j = 0; j < 4; j++) {
            int n = n0 + wn * 32 + j * 8 + t * 2;
            #pragma unroll
            for (int h = 0; h < 2; h++) {
                int m = m0 + wm * 64 + i * 16 + g + h * 8;
                *(float2*)(E + ((size_t)z * LA + m) * LB + n) =
                    make_float2(acc[i][j][h*2+0], acc[i][j][h*2+1]);
            }
        }

    // ---- partial row/col softmax stats (on-chip) ----
    __syncthreads();
    float* scr   = (float*)(smc + 2 * G1_STAGE);
    float* srmax = scr;            // [128][4]
    float* srsum = scr + 512;      // [128][4]
    float* srm   = scr + 1024;     // [128]
    float* scmax = scr + 1152;     // [128][2]
    float* scsum = scr + 1408;     // [128][2]
    float* scm   = scr + 1664;     // [128]

    #pragma unroll
    for (int i = 0; i < 4; i++)
        #pragma unroll
        for (int h = 0; h < 2; h++) {
            float mv = -3.4e38f;
            #pragma unroll
            for (int j = 0; j < 4; j++) {
                mv = fmaxf(mv, acc[i][j][h*2+0]);
                mv = fmaxf(mv, acc[i][j][h*2+1]);
            }
            mv = fmaxf(mv, __shfl_xor_sync(0xFFFFFFFFu, mv, 1));
            mv = fmaxf(mv, __shfl_xor_sync(0xFFFFFFFFu, mv, 2));
            if (t == 0) srmax[(wm*64 + i*16 + g + h*8) * 4 + wn] = mv;
        }
    __syncthreads();
    if (tid < 128)
        srm[tid] = fmaxf(fmaxf(srmax[tid*4+0], srmax[tid*4+1]),
                         fmaxf(srmax[tid*4+2], srmax[tid*4+3]));
    __syncthreads();
    #pragma unroll
    for (int i = 0; i < 4; i++)
        #pragma unroll
        for (int h = 0; h < 2; h++) {
            int row = wm*64 + i*16 + g + h*8;
            float rm = srm[row], s = 0.f;
            #pragma unroll
            for (int j = 0; j < 4; j++) {
                s += __expf(acc[i][j][h*2+0] - rm);
                s += __expf(acc[i][j][h*2+1] - rm);
            }
            s += __shfl_xor_sync(0xFFFFFFFFu, s, 1);
            s += __shfl_xor_sync(0xFFFFFFFFu, s, 2);
            if (t == 0) srsum[row * 4 + wn] = s;
        }
    __syncthreads();
    if (tid < 128) {
        size_t o = (size_t)blockIdx.x * NROW + z * 512 + m0 + tid;
        g_rpmax[o] = srm[tid];
        g_rpsum[o] = srsum[tid*4+0] + srsum[tid*4+1] + srsum[tid*4+2] + srsum[tid*4+3];
    }

    #pragma unroll
    for (int j = 0; j < 4; j++)
        #pragma unroll
        for (int rl = 0; rl < 2; rl++) {
            float mv = -3.4e38f;
            #pragma unroll
            for (int i = 0; i < 4; i++) {
                mv = fmaxf(mv, acc[i][j][rl]);
                mv = fmaxf(mv, acc[i][j][2+rl]);
            }
            mv = fmaxf(mv, __shfl_xor_sync(0xFFFFFFFFu, mv, 4));
            mv = fmaxf(mv, __shfl_xor_sync(0xFFFFFFFFu, mv, 8));
            mv = fmaxf(mv, __shfl_xor_sync(0xFFFFFFFFu, mv, 16));
            if (g == 0) scmax[(wn*32 + j*8 + t*2 + rl) * 2 + wm] = mv;
        }
    __syncthreads();
    if (tid < 128) scm[tid] = fmaxf(scmax[tid*2], scmax[tid*2+1]);
    __syncthreads();
    #pragma unroll
    for (int j = 0; j < 4; j++)
        #pragma unroll
        for (int rl = 0; rl < 2; rl++) {
            int col = wn*32 + j*8 + t*2 + rl;
            float cm = scm[col], s = 0.f;
            #pragma unroll
            for (int i = 0; i < 4; i++) {
                s += __expf(acc[i][j][rl] - cm);
                s += __expf(acc[i][j][2+rl] - cm);
            }
            s += __shfl_xor_sync(0xFFFFFFFFu, s, 4);
            s += __shfl_xor_sync(0xFFFFFFFFu, s, 8);
            s += __shfl_xor_sync(0xFFFFFFFFu, s, 16);
            if (g == 0) scsum[col * 2 + wm] = s;
        }
    __syncthreads();
    if (tid < 128) {
        size_t o = (size_t)blockIdx.y * NROW + z * 512 + n0 + tid;
        g_cpmax[o] = scm[tid];
        g_cpsum[o] = scsum[tid*2] + scsum[tid*2+1];
    }
}

// ---------------- reduce 4 partials -> max + 1/sum ---------------------------
__global__ __launch_bounds__(256)
void reduce_stats_k()
{
    int idx = blockIdx.x * 256 + threadIdx.x;   // 0..NROW-1
    const float* pm = blockIdx.y ? g_cpmax : g_rpmax;
    const float* ps = blockIdx.y ? g_cpsum : g_rpsum;
    float m = -3.4e38f;
    #pragma unroll
    for (int p = 0; p < 4; p++) m = fmaxf(m, pm[p * NROW + idx]);
    float s = 0.f;
    #pragma unroll
    for (int p = 0; p < 4; p++) s += ps[p * NROW + idx] * __expf(pm[p * NROW + idx] - m);
    if (blockIdx.y) { g_colm[idx] = m; g_coli[idx] = 1.f / s; }
    else            { g_rowm[idx] = m; g_rowi[idx] = 1.f / s; }
}

// =============================================================================
// GEMM_PV: C = P (Bh+Bl)^T with on-the-fly P. hi pass f32 acc, lo pass f16 acc.
// =============================================================================
#define PV_STAGE (3*TILE_BYTES)
#define PV_SMEM (2*PV_STAGE + 2048)

template<bool TRANSA>
__global__ __launch_bounds__(256)
void gemm_pv(const float* __restrict__ E,
             const float* __restrict__ Msc, const float* __restrict__ Isc,
             const __half* __restrict__ Bh, const __half* __restrict__ Bl,
             const float* __restrict__ Obase, float* __restrict__ Out)
{
    const int M = 512, N = DIM, K = 512;
    extern __shared__ char smraw[];
    uint32_t sm0 = smem_to_u32(smraw);
    uint32_t smb = (sm0 + 1023u) & ~1023u;
    char* smc = smraw + (smb - sm0);

    const int tid = threadIdx.x;
    const int lid = tid & 31, wid = tid >> 5;
    const int wm = wid >> 2, wn = wid & 3;
    const int z = blockIdx.z, m0 = blockIdx.y * 128, n0 = blockIdx.x * 128;

    float* sm_m = (float*)(smc + 2 * PV_STAGE);
    float* sm_i = sm_m + 128;
    if (tid < 128) {
        sm_m[tid] = Msc[z * 512 + m0 + tid];
        sm_i[tid] = Isc[z * 512 + m0 + tid];
    }

    const __half* srcB[2] = { Bh + ((size_t)z * N + n0) * K,
                              Bl + ((size_t)z * N + n0) * K };

    const int ar  = (lid & 7) | (((lid >> 3) & 1) << 3);
    const int akh = lid >> 4;
    uint32_t aoff[4];
    #pragma unroll
    for (int i = 0; i < 4; i++)
        aoff[i] = sw_off(wm * 64 + i * 16 + ar, akh);
    const int br  = (lid & 7) | ((lid >> 4) << 3);
    const int bkh = (lid >> 3) & 1;
    uint32_t boff[2];
    #pragma unroll
    for (int j2 = 0; j2 < 2; j2++)
        boff[j2] = sw_off(wn * 32 + j2 * 16 + br, bkh);

    float acc[4][4][4];
    uint32_t alo[4][4][2];
    #pragma unroll
    for (int i = 0; i < 4; i++)
        #pragma unroll
        for (int j = 0; j < 4; j++) {
            #pragma unroll
            for (int r = 0; r < 4; r++) acc[i][j][r] = 0.f;
            alo[i][j][0] = 0u; alo[i][j][1] = 0u;
        }

    const int nk = K >> 5;   // 16

    auto issueB = [&](int s, int kt) {
        uint32_t sb = smb + s * PV_STAGE;
        #pragma unroll
        for (int tl = 0; tl < 2; tl++) {
            uint32_t tb = sb + (tl + 1) * TILE_BYTES;
            #pragma unroll
            for (int it = 0; it < 2; it++) {
                int idx = tid + it * 256;
                int m = idx >> 2, ks = (idx >> 1) & 1, kh = idx & 1;
                cp16(tb + ks * 4096 + sw_off(m, kh),
                     srcB[tl] + (size_t)m * K + kt * 32 + ks * 16 + kh * 8);
            }
        }
    };

    auto fillA = [&](int s, int kt) {
        char* tb = smc + s * PV_STAGE;   // A at offset 0
        if (!TRANSA) {
            #pragma unroll
            for (int it = 0; it < 4; it++) {
                int a = (tid >> 3) + it * 32;
                int c4 = (tid & 7) * 4;
                float4 v = *(const float4*)(E + ((size_t)z * M + m0 + a) * K + kt * 32 + c4);
                float rm = sm_m[a], ri = sm_i[a];
                __half2 h01 = __floats2half2_rn(__expf(v.x - rm) * ri, __expf(v.y - rm) * ri);
                __half2 h23 = __floats2half2_rn(__expf(v.z - rm) * ri, __expf(v.w - rm) * ri);
                int ks = c4 >> 4, within = c4 & 15;
                uint32_t off = (uint32_t)(ks * 4096) + sw_off(a, within >> 3) + (within & 7) * 2;
                *(__half2*)(tb + off)     = h01;
                *(__half2*)(tb + off + 4) = h23;
            }
        } else {
            int k4 = (tid >> 5) * 4;
            #pragma unroll
            for (int it = 0; it < 4; it++) {
                int c = (tid & 31) + it * 32;
                float cm = sm_m[c], ci = sm_i[c];
                float p[4];
                #pragma unroll
                for (int ik = 0; ik < 4; ik++) {
                    float v = E[((size_t)z * 512 + kt * 32 + k4 + ik) * 512 + m0 + c];
                    p[ik] = __expf(v - cm) * ci;
                }
                __half2 h01 = __floats2half2_rn(p[0], p[1]);
                __half2 h23 = __floats2half2_rn(p[2], p[3]);
                int ks = k4 >> 4, within = k4 & 15;
                uint32_t off = (uint32_t)(ks * 4096) + sw_off(c, within >> 3) + (within & 7) * 2;
                *(__half2*)(tb + off)     = h01;
                *(__half2*)(tb + off + 4) = h23;
            }
        }
    };

    issueB(0, 0);
    cp_commit();
    __syncthreads();          // sm_m/sm_i ready
    fillA(0, 0);

    for (int kt = 0; kt < nk; kt++) {
        int s = kt & 1;
        if (kt + 1 < nk) { issueB(s ^ 1, kt + 1); cp_commit(); cp_wait1(); }
        else             { cp_wait0(); }
        __syncthreads();

        uint32_t st = smb + s * PV_STAGE;
        #pragma unroll
        for (int ks = 0; ks < 2; ks++) {
            uint32_t a_f[4][4], b_h[4][2], b_l[4][2];
            #pragma unroll
            for (int i = 0; i < 4; i++)
                ldsm4(a_f[i], st + ks * 4096 + aoff[i]);
            #pragma unroll
            for (int j2 = 0; j2 < 2; j2++) {
                uint32_t rh[4], rl[4];
                ldsm4(rh, st + 1 * TILE_BYTES + ks * 4096 + boff[j2]);
                ldsm4(rl, st + 2 * TILE_BYTES + ks * 4096 + boff[j2]);
                b_h[j2*2+0][0] = rh[0]; b_h[j2*2+0][1] = rh[1];
                b_h[j2*2+1][0] = rh[2]; b_h[j2*2+1][1] = rh[3];
                b_l[j2*2+0][0] = rl[0]; b_l[j2*2+0][1] = rl[1];
                b_l[j2*2+1][0] = rl[2]; b_l[j2*2+1][1] = rl[3];
            }
            #pragma unroll
            for (int i = 0; i < 4; i++)
                #pragma unroll
                for (int j = 0; j < 4; j++) {
                    mma_f16(acc[i][j], a_f[i], b_h[j]);        // hi: f32 acc
                    mma_f16acc(alo[i][j], a_f[i], b_l[j]);     // lo: f16 acc
                }
        }
        if (kt + 1 < nk) fillA(s ^ 1, kt + 1);
        __syncthreads();
    }

    // ---- ESIM epilogue (merge f16 partials first) ----
    const int g = lid >> 2, t = lid & 3;
    #pragma unroll
    for (int i = 0; i < 4; i++)
        #pragma unroll
        for (int j = 0; j < 4; j++) {
            merge_lo(acc[i][j], alo[i][j]);
            int n = n0 + wn * 32 + j * 8 + t * 2;
            #pragma unroll
            for (int h = 0; h < 2; h++) {
                int m = m0 + wm * 64 + i * 16 + g + h * 8;
                float2 v = make_float2(acc[i][j][h*2+0], acc[i][j][h*2+1]);
                float2 av = *(const float2*)(Obase + ((size_t)z * M + m) * DIM + n);
                float* orow = Out + ((size_t)z * M + m) * OUTC + n;
                *(float2*)(orow)         = av;
                *(float2*)(orow + DIM)   = v;
                *(float2*)(orow + 2*DIM) = make_float2(av.x - v.x, av.y - v.y);
                *(float2*)(orow + 3*DIM) = make_float2(av.x * v.x, av.y * v.y);
            }
        }
}

// ---------------- fp16 split + transpose of fp32 input ----------------------
__global__ __launch_bounds__(256)
void conv_split_T(const float* __restrict__ X,
                  __half* __restrict__ Xh,  __half* __restrict__ Xl,
                  __half* __restrict__ XTh, __half* __restrict__ XTl,
                  int R, int C)
{
    __shared__ __half sh[64][65], sl[64][65];
    int z = blockIdx.z, r0 = blockIdx.y * 64, c0 = blockIdx.x * 64;
    #pragma unroll
    for (int it = 0; it < 16; it++) {
        int idx = threadIdx.x + it * 256;
        int i = idx >> 6, j = idx & 63;
        float v = X[((size_t)z * R + r0 + i) * C + c0 + j];
        __half h = __float2half_rn(v);
        __half l = __float2half_rn(v - __half2float(h));
        Xh[((size_t)z * R + r0 + i) * C + c0 + j] = h;
        Xl[((size_t)z * R + r0 + i) * C + c0 + j] = l;
        sh[i][j] = h; sl[i][j] = l;
    }
    __syncthreads();
    #pragma unroll
    for (int it = 0; it < 16; it++) {
        int idx = threadIdx.x + it * 256;
        int j = idx >> 6, i = idx & 63;
        XTh[((size_t)z * C + c0 + j) * R + r0 + i] = sh[i][j];
        XTl[((size_t)z * C + c0 + j) * R + r0 + i] = sl[i][j];
    }
}

// ---------------------------------------------------------------------------
extern "C" void kernel_launch(void* const* d_in, const int* in_sizes, int n_in,
                              void* d_out, int out_size)
{
    const float* a_bar = (const float*)d_in[0];
    const float* b_bar = (const float*)d_in[1];
    float* out = (float*)d_out;
    float* m_a = out;
    float* m_b = out + (size_t)NB * LA * OUTC;

    __half *ah, *al, *bh, *bl, *aTh, *aTl, *bTh, *bTl;
    float *pe, *prm, *pri, *pcm, *pci;
    cudaGetSymbolAddress((void**)&ah,  g_ah);   cudaGetSymbolAddress((void**)&al,  g_al);
    cudaGetSymbolAddress((void**)&bh,  g_bh);   cudaGetSymbolAddress((void**)&bl,  g_bl);
    cudaGetSymbolAddress((void**)&aTh, g_aTh);  cudaGetSymbolAddress((void**)&aTl, g_aTl);
    cudaGetSymbolAddress((void**)&bTh, g_bTh);  cudaGetSymbolAddress((void**)&bTl, g_bTl);
    cudaGetSymbolAddress((void**)&pe,  g_e);
    cudaGetSymbolAddress((void**)&prm, g_rowm); cudaGetSymbolAddress((void**)&pri, g_rowi);
    cudaGetSymbolAddress((void**)&pcm, g_colm); cudaGetSymbolAddress((void**)&pci, g_coli);

    cudaFuncSetAttribute(gemm1_k, cudaFuncAttributeMaxDynamicSharedMemorySize, G1_SMEM);
    cudaFuncSetAttribute(gemm_pv<false>, cudaFuncAttributeMaxDynamicSharedMemorySize, PV_SMEM);
    cudaFuncSetAttribute(gemm_pv<true>,  cudaFuncAttributeMaxDynamicSharedMemorySize, PV_SMEM);

    // 1) fp16 split + transposed copies of inputs
    conv_split_T<<<dim3(DIM/64, LA/64, NB), 256>>>(a_bar, ah, al, aTh, aTl, LA, DIM);
    conv_split_T<<<dim3(DIM/64, LB/64, NB), 256>>>(b_bar, bh, bl, bTh, bTl, LB, DIM);

    // 2) e = a @ b^T + on-chip row/col partial softmax stats
    gemm1_k<<<dim3(LB/128, LA/128, NB), 256, G1_SMEM>>>(ah, al, bh, bl, pe);

    // 3) reduce partials -> rowmax/rowinv, colmax/colinv
    reduce_stats_k<<<dim3(NROW/256, 2), 256>>>();

    // 4) m_a: a_tilde = softmax_row(e) @ b   (P built on the fly from e)
    gemm_pv<false><<<dim3(DIM/128, LA/128, NB), 256, PV_SMEM>>>(
        pe, prm, pri, bTh, bTl, a_bar, m_a);

    // 5) m_b: b_tilde = softmax_col(e)^T @ a (P^T built on the fly from e)
    gemm_pv<true><<<dim3(DIM/128, LB/128, NB), 256, PV_SMEM>>>(
        pe, pcm, pci, aTh, aTl, b_bar, m_b);
}

// round 8
// speedup vs baseline: 1.6007x; 1.6007x over previous
#include <cuda_runtime.h>
#include <cuda_fp16.h>
#include <cstdint>

#define NB   32
#define LA   512
#define LB   512
#define DIM  768
#define OUTC 3072
#define NROW (NB*512)   // 16384 scalar slots

// ---------------- scratch (__device__ globals; no allocation allowed) -------
__device__ __align__(1024) __half g_ah [(size_t)NB*LA*DIM], g_al [(size_t)NB*LA*DIM];
__device__ __align__(1024) __half g_bh [(size_t)NB*LB*DIM], g_bl [(size_t)NB*LB*DIM];
__device__ __align__(1024) __half g_aTh[(size_t)NB*DIM*LA];
__device__ __align__(1024) __half g_bTh[(size_t)NB*DIM*LB];
__device__ __align__(1024) float g_e[(size_t)NB*LA*LB];
__device__ float g_rpmax[4*NROW], g_rpsum[4*NROW];
__device__ float g_cpmax[4*NROW], g_cpsum[4*NROW];
__device__ float g_rowm[NROW], g_rowi[NROW], g_colm[NROW], g_coli[NROW];

// ---------------- low-level helpers (portable PTX only) ---------------------
__device__ __forceinline__ uint32_t smem_to_u32(const void* p) {
    uint32_t a;
    asm("{ .reg .u64 t; cvta.to.shared.u64 t, %1; cvt.u32.u64 %0, t; }" : "=r"(a) : "l"(p));
    return a;
}
__device__ __forceinline__ void cp16(uint32_t dst, const void* src) {
    asm volatile("cp.async.cg.shared.global [%0], [%1], 16;" :: "r"(dst), "l"(src));
}
__device__ __forceinline__ void cp_commit() { asm volatile("cp.async.commit_group;"); }
__device__ __forceinline__ void cp_wait1()  { asm volatile("cp.async.wait_group 1;"); }
__device__ __forceinline__ void cp_wait0()  { asm volatile("cp.async.wait_group 0;"); }

__device__ __forceinline__ void ldsm4(uint32_t* r, uint32_t addr) {
    asm volatile("ldmatrix.sync.aligned.m8n8.x4.shared.b16 {%0,%1,%2,%3}, [%4];"
                 : "=r"(r[0]), "=r"(r[1]), "=r"(r[2]), "=r"(r[3]) : "r"(addr));
}
__device__ __forceinline__ void mma_f16(float* c, const uint32_t* a, const uint32_t* b) {
    asm volatile("mma.sync.aligned.m16n8k16.row.col.f32.f16.f16.f32 "
                 "{%0,%1,%2,%3}, {%4,%5,%6,%7}, {%8,%9}, {%0,%1,%2,%3};"
                 : "+f"(c[0]), "+f"(c[1]), "+f"(c[2]), "+f"(c[3])
                 : "r"(a[0]), "r"(a[1]), "r"(a[2]), "r"(a[3]), "r"(b[0]), "r"(b[1]));
}

#define TILE_BYTES 8192            // 128 rows x 32 halfs

// swizzled smem byte offset inside a tile for (row, 16B-chunk kh)
__device__ __forceinline__ uint32_t sw_off(int row, int kh) {
    return (uint32_t)(row * 32 + ((kh ^ ((row >> 2) & 1)) << 4));
}

// =============================================================================
// GEMM1: e = (Ah+Al)(Bh+Bl)^T, 3 passes f32 acc, e store + partial stats.
// =============================================================================
#define G1_STAGE (4*TILE_BYTES)
#define G1_SCRATCH 8192
#define G1_SMEM (2*G1_STAGE + G1_SCRATCH + 1024)

__global__ __launch_bounds__(256)
void gemm1_k(const __half* __restrict__ Ah, const __half* __restrict__ Al,
             const __half* __restrict__ Bh, const __half* __restrict__ Bl,
             float* __restrict__ E)
{
    extern __shared__ char smraw[];
    uint32_t sm0 = smem_to_u32(smraw);
    uint32_t smb = (sm0 + 1023u) & ~1023u;
    char* smc = smraw + (smb - sm0);

    const int tid = threadIdx.x;
    const int lid = tid & 31, wid = tid >> 5;
    const int wm = wid >> 2, wn = wid & 3;
    const int g = lid >> 2, t = lid & 3;
    const int z = blockIdx.z, m0 = blockIdx.y * 128, n0 = blockIdx.x * 128;
    const int K = DIM;

    const __half* srcs[4] = {
        Ah + ((size_t)z * LA + m0) * K, Al + ((size_t)z * LA + m0) * K,
        Bh + ((size_t)z * LB + n0) * K, Bl + ((size_t)z * LB + n0) * K };

    const int ar  = (lid & 7) | (((lid >> 3) & 1) << 3);
    const int akh = lid >> 4;
    uint32_t aoff[4];
    #pragma unroll
    for (int i = 0; i < 4; i++)
        aoff[i] = sw_off(wm * 64 + i * 16 + ar, akh);
    const int br  = (lid & 7) | ((lid >> 4) << 3);
    const int bkh = (lid >> 3) & 1;
    uint32_t boff[2];
    #pragma unroll
    for (int j2 = 0; j2 < 2; j2++)
        boff[j2] = sw_off(wn * 32 + j2 * 16 + br, bkh);

    float acc[4][4][4];
    #pragma unroll
    for (int i = 0; i < 4; i++)
        #pragma unroll
        for (int j = 0; j < 4; j++)
            #pragma unroll
            for (int r = 0; r < 4; r++) acc[i][j][r] = 0.f;

    const int nk = K >> 5;

    auto issue_stage = [&](int s, int kt) {
        uint32_t sb = smb + s * G1_STAGE;
        #pragma unroll
        for (int tl = 0; tl < 4; tl++) {
            const __half* src = srcs[tl];
            uint32_t tb = sb + tl * TILE_BYTES;
            #pragma unroll
            for (int it = 0; it < 2; it++) {
                int idx = tid + it * 256;
                int m = idx >> 2, ks = (idx >> 1) & 1, kh = idx & 1;
                cp16(tb + ks * 4096 + sw_off(m, kh),
                     src + (size_t)m * K + kt * 32 + ks * 16 + kh * 8);
            }
        }
    };

    issue_stage(0, 0);
    cp_commit();

    for (int kt = 0; kt < nk; kt++) {
        if (kt + 1 < nk) { issue_stage((kt + 1) & 1, kt + 1); }
        cp_commit();
        cp_wait1();
        __syncthreads();

        uint32_t st = smb + (kt & 1) * G1_STAGE;
        #pragma unroll
        for (int ks = 0; ks < 2; ks++) {
            uint32_t a_h[4][4], a_l[4][4], b_h[4][2], b_l[4][2];
            #pragma unroll
            for (int i = 0; i < 4; i++) {
                ldsm4(a_h[i], st + 0 * TILE_BYTES + ks * 4096 + aoff[i]);
                ldsm4(a_l[i], st + 1 * TILE_BYTES + ks * 4096 + aoff[i]);
            }
            #pragma unroll
            for (int j2 = 0; j2 < 2; j2++) {
                uint32_t rh[4], rl[4];
                ldsm4(rh, st + 2 * TILE_BYTES + ks * 4096 + boff[j2]);
                ldsm4(rl, st + 3 * TILE_BYTES + ks * 4096 + boff[j2]);
                b_h[j2*2+0][0] = rh[0]; b_h[j2*2+0][1] = rh[1];
                b_h[j2*2+1][0] = rh[2]; b_h[j2*2+1][1] = rh[3];
                b_l[j2*2+0][0] = rl[0]; b_l[j2*2+0][1] = rl[1];
                b_l[j2*2+1][0] = rl[2]; b_l[j2*2+1][1] = rl[3];
            }
            #pragma unroll
            for (int i = 0; i < 4; i++)
                #pragma unroll
                for (int j = 0; j < 4; j++) {
                    mma_f16(acc[i][j], a_h[i], b_h[j]);
                    mma_f16(acc[i][j], a_h[i], b_l[j]);
                    mma_f16(acc[i][j], a_l[i], b_h[j]);
                }
        }
        __syncthreads();
    }

    // ---- store e (fp32) ----
    #pragma unroll
    for (int i = 0; i < 4; i++)
        #pragma unroll
        for (int j = 0; j < 4; j++) {
            int n = n0 + wn * 32 + j * 8 + t * 2;
            #pragma unroll
            for (int h = 0; h < 2; h++) {
                int m = m0 + wm * 64 + i * 16 + g + h * 8;
                *(float2*)(E + ((size_t)z * LA + m) * LB + n) =
                    make_float2(acc[i][j][h*2+0], acc[i][j][h*2+1]);
            }
        }

    // ---- partial row/col softmax stats (on-chip) ----
    __syncthreads();
    float* scr   = (float*)(smc + 2 * G1_STAGE);
    float* srmax = scr;            // [128][4]
    float* srsum = scr + 512;      // [128][4]
    float* srm   = scr + 1024;     // [128]
    float* scmax = scr + 1152;     // [128][2]
    float* scsum = scr + 1408;     // [128][2]
    float* scm   = scr + 1664;     // [128]

    #pragma unroll
    for (int i = 0; i < 4; i++)
        #pragma unroll
        for (int h = 0; h < 2; h++) {
            float mv = -3.4e38f;
            #pragma unroll
            for (int j = 0; j < 4; j++) {
                mv = fmaxf(mv, acc[i][j][h*2+0]);
                mv = fmaxf(mv, acc[i][j][h*2+1]);
            }
            mv = fmaxf(mv, __shfl_xor_sync(0xFFFFFFFFu, mv, 1));
            mv = fmaxf(mv, __shfl_xor_sync(0xFFFFFFFFu, mv, 2));
            if (t == 0) srmax[(wm*64 + i*16 + g + h*8) * 4 + wn] = mv;
        }
    __syncthreads();
    if (tid < 128)
        srm[tid] = fmaxf(fmaxf(srmax[tid*4+0], srmax[tid*4+1]),
                         fmaxf(srmax[tid*4+2], srmax[tid*4+3]));
    __syncthreads();
    #pragma unroll
    for (int i = 0; i < 4; i++)
        #pragma unroll
        for (int h = 0; h < 2; h++) {
            int row = wm*64 + i*16 + g + h*8;
            float rm = srm[row], s = 0.f;
            #pragma unroll
            for (int j = 0; j < 4; j++) {
                s += __expf(acc[i][j][h*2+0] - rm);
                s += __expf(acc[i][j][h*2+1] - rm);
            }
            s += __shfl_xor_sync(0xFFFFFFFFu, s, 1);
            s += __shfl_xor_sync(0xFFFFFFFFu, s, 2);
            if (t == 0) srsum[row * 4 + wn] = s;
        }
    __syncthreads();
    if (tid < 128) {
        size_t o = (size_t)blockIdx.x * NROW + z * 512 + m0 + tid;
        g_rpmax[o] = srm[tid];
        g_rpsum[o] = srsum[tid*4+0] + srsum[tid*4+1] + srsum[tid*4+2] + srsum[tid*4+3];
    }

    #pragma unroll
    for (int j = 0; j < 4; j++)
        #pragma unroll
        for (int rl = 0; rl < 2; rl++) {
            float mv = -3.4e38f;
            #pragma unroll
            for (int i = 0; i < 4; i++) {
                mv = fmaxf(mv, acc[i][j][rl]);
                mv = fmaxf(mv, acc[i][j][2+rl]);
            }
            mv = fmaxf(mv, __shfl_xor_sync(0xFFFFFFFFu, mv, 4));
            mv = fmaxf(mv, __shfl_xor_sync(0xFFFFFFFFu, mv, 8));
            mv = fmaxf(mv, __shfl_xor_sync(0xFFFFFFFFu, mv, 16));
            if (g == 0) scmax[(wn*32 + j*8 + t*2 + rl) * 2 + wm] = mv;
        }
    __syncthreads();
    if (tid < 128) scm[tid] = fmaxf(scmax[tid*2], scmax[tid*2+1]);
    __syncthreads();
    #pragma unroll
    for (int j = 0; j < 4; j++)
        #pragma unroll
        for (int rl = 0; rl < 2; rl++) {
            int col = wn*32 + j*8 + t*2 + rl;
            float cm = scm[col], s = 0.f;
            #pragma unroll
            for (int i = 0; i < 4; i++) {
                s += __expf(acc[i][j][rl] - cm);
                s += __expf(acc[i][j][2+rl] - cm);
            }
            s += __shfl_xor_sync(0xFFFFFFFFu, s, 4);
            s += __shfl_xor_sync(0xFFFFFFFFu, s, 8);
            s += __shfl_xor_sync(0xFFFFFFFFu, s, 16);
            if (g == 0) scsum[col * 2 + wm] = s;
        }
    __syncthreads();
    if (tid < 128) {
        size_t o = (size_t)blockIdx.y * NROW + z * 512 + n0 + tid;
        g_cpmax[o] = scm[tid];
        g_cpsum[o] = scsum[tid*2] + scsum[tid*2+1];
    }
}

// ---------------- reduce 4 partials -> max + 1/sum ---------------------------
__global__ __launch_bounds__(256)
void reduce_stats_k()
{
    int idx = blockIdx.x * 256 + threadIdx.x;
    const float* pm = blockIdx.y ? g_cpmax : g_rpmax;
    const float* ps = blockIdx.y ? g_cpsum : g_rpsum;
    float m = -3.4e38f;
    #pragma unroll
    for (int p = 0; p < 4; p++) m = fmaxf(m, pm[p * NROW + idx]);
    float s = 0.f;
    #pragma unroll
    for (int p = 0; p < 4; p++) s += ps[p * NROW + idx] * __expf(pm[p * NROW + idx] - m);
    if (blockIdx.y) { g_colm[idx] = m; g_coli[idx] = 1.f / s; }
    else            { g_rowm[idx] = m; g_rowi[idx] = 1.f / s; }
}

// =============================================================================
// GEMM_PV: C = P Bh^T, single fp16 pass. P built on the fly from e.
// =============================================================================
#define PV_STAGE (2*TILE_BYTES)
#define PV_SMEM (2*PV_STAGE + 2048)

template<bool TRANSA>
__global__ __launch_bounds__(256)
void gemm_pv(const float* __restrict__ E,
             const float* __restrict__ Msc, const float* __restrict__ Isc,
             const __half* __restrict__ Bh,
             const float* __restrict__ Obase, float* __restrict__ Out)
{
    const int M = 512, N = DIM, K = 512;
    extern __shared__ char smraw[];
    uint32_t sm0 = smem_to_u32(smraw);
    uint32_t smb = (sm0 + 1023u) & ~1023u;
    char* smc = smraw + (smb - sm0);

    const int tid = threadIdx.x;
    const int lid = tid & 31, wid = tid >> 5;
    const int wm = wid >> 2, wn = wid & 3;
    const int z = blockIdx.z, m0 = blockIdx.y * 128, n0 = blockIdx.x * 128;

    float* sm_m = (float*)(smc + 2 * PV_STAGE);
    float* sm_i = sm_m + 128;
    if (tid < 128) {
        sm_m[tid] = Msc[z * 512 + m0 + tid];
        sm_i[tid] = Isc[z * 512 + m0 + tid];
    }

    const __half* srcB = Bh + ((size_t)z * N + n0) * K;

    const int ar  = (lid & 7) | (((lid >> 3) & 1) << 3);
    const int akh = lid >> 4;
    uint32_t aoff[4];
    #pragma unroll
    for (int i = 0; i < 4; i++)
        aoff[i] = sw_off(wm * 64 + i * 16 + ar, akh);
    const int br  = (lid & 7) | ((lid >> 4) << 3);
    const int bkh = (lid >> 3) & 1;
    uint32_t boff[2];
    #pragma unroll
    for (int j2 = 0; j2 < 2; j2++)
        boff[j2] = sw_off(wn * 32 + j2 * 16 + br, bkh);

    float acc[4][4][4];
    #pragma unroll
    for (int i = 0; i < 4; i++)
        #pragma unroll
        for (int j = 0; j < 4; j++)
            #pragma unroll
            for (int r = 0; r < 4; r++) acc[i][j][r] = 0.f;

    const int nk = K >> 5;   // 16

    auto issueB = [&](int s, int kt) {
        uint32_t tb = smb + s * PV_STAGE + TILE_BYTES;
        #pragma unroll
        for (int it = 0; it < 2; it++) {
            int idx = tid + it * 256;
            int m = idx >> 2, ks = (idx >> 1) & 1, kh = idx & 1;
            cp16(tb + ks * 4096 + sw_off(m, kh),
                 srcB + (size_t)m * K + kt * 32 + ks * 16 + kh * 8);
        }
    };

    // build A tile (fp16 P), one 16B swizzled chunk (8 halfs) per thread-iter
    auto fillA = [&](int s, int kt) {
        char* tb = smc + s * PV_STAGE;   // A at offset 0
        if (!TRANSA) {
            #pragma unroll
            for (int it = 0; it < 2; it++) {
                int c = tid + it * 256;          // 0..511 chunks
                int row = c >> 2, kc = c & 3;    // kc: 8-half group in row
                const float* ep = E + ((size_t)z * M + m0 + row) * K + kt * 32 + kc * 8;
                float4 v0 = *(const float4*)(ep);
                float4 v1 = *(const float4*)(ep + 4);
                float rm = sm_m[row], ri = sm_i[row];
                __half2 h0 = __floats2half2_rn(__expf(v0.x - rm) * ri, __expf(v0.y - rm) * ri);
                __half2 h1 = __floats2half2_rn(__expf(v0.z - rm) * ri, __expf(v0.w - rm) * ri);
                __half2 h2 = __floats2half2_rn(__expf(v1.x - rm) * ri, __expf(v1.y - rm) * ri);
                __half2 h3 = __floats2half2_rn(__expf(v1.z - rm) * ri, __expf(v1.w - rm) * ri);
                uint32_t off = (uint32_t)((kc >> 1) * 4096) + sw_off(row, kc & 1);
                uint4 pk;
                pk.x = *(uint32_t*)&h0; pk.y = *(uint32_t*)&h1;
                pk.z = *(uint32_t*)&h2; pk.w = *(uint32_t*)&h3;
                *(uint4*)(tb + off) = pk;
            }
        } else {
            #pragma unroll
            for (int it = 0; it < 2; it++) {
                int c = tid + it * 256;
                int col = c & 127, kc = c >> 7;  // lanes -> consecutive cols
                float cm = sm_m[col], ci = sm_i[col];
                float p[8];
                #pragma unroll
                for (int ik = 0; ik < 8; ik++) {
                    float v = E[((size_t)z * 512 + kt * 32 + kc * 8 + ik) * 512 + m0 + col];
                    p[ik] = __expf(v - cm) * ci;
                }
                __half2 h0 = __floats2half2_rn(p[0], p[1]);
                __half2 h1 = __floats2half2_rn(p[2], p[3]);
                __half2 h2 = __floats2half2_rn(p[4], p[5]);
                __half2 h3 = __floats2half2_rn(p[6], p[7]);
                uint32_t off = (uint32_t)((kc >> 1) * 4096) + sw_off(col, kc & 1);
                uint4 pk;
                pk.x = *(uint32_t*)&h0; pk.y = *(uint32_t*)&h1;
                pk.z = *(uint32_t*)&h2; pk.w = *(uint32_t*)&h3;
                *(uint4*)(tb + off) = pk;
            }
        }
    };

    issueB(0, 0);
    cp_commit();
    __syncthreads();          // sm_m/sm_i ready
    fillA(0, 0);

    for (int kt = 0; kt < nk; kt++) {
        int s = kt & 1;
        if (kt + 1 < nk) { issueB(s ^ 1, kt + 1); cp_commit(); cp_wait1(); }
        else             { cp_wait0(); }
        __syncthreads();

        uint32_t st = smb + s * PV_STAGE;
        #pragma unroll
        for (int ks = 0; ks < 2; ks++) {
            uint32_t a_f[4][4], b_h[4][2];
            #pragma unroll
            for (int i = 0; i < 4; i++)
                ldsm4(a_f[i], st + ks * 4096 + aoff[i]);
            #pragma unroll
            for (int j2 = 0; j2 < 2; j2++) {
                uint32_t rh[4];
                ldsm4(rh, st + TILE_BYTES + ks * 4096 + boff[j2]);
                b_h[j2*2+0][0] = rh[0]; b_h[j2*2+0][1] = rh[1];
                b_h[j2*2+1][0] = rh[2]; b_h[j2*2+1][1] = rh[3];
            }
            #pragma unroll
            for (int i = 0; i < 4; i++)
                #pragma unroll
                for (int j = 0; j < 4; j++)
                    mma_f16(acc[i][j], a_f[i], b_h[j]);
        }
        if (kt + 1 < nk) fillA(s ^ 1, kt + 1);
        __syncthreads();
    }

    // ---- ESIM epilogue ----
    const int g = lid >> 2, t = lid & 3;
    #pragma unroll
    for (int i = 0; i < 4; i++)
        #pragma unroll
        for (int j = 0; j < 4; j++) {
            int n = n0 + wn * 32 + j * 8 + t * 2;
            #pragma unroll
            for (int h = 0; h < 2; h++) {
                int m = m0 + wm * 64 + i * 16 + g + h * 8;
                float2 v = make_float2(acc[i][j][h*2+0], acc[i][j][h*2+1]);
                float2 av = *(const float2*)(Obase + ((size_t)z * M + m) * DIM + n);
                float* orow = Out + ((size_t)z * M + m) * OUTC + n;
                *(float2*)(orow)         = av;
                *(float2*)(orow + DIM)   = v;
                *(float2*)(orow + 2*DIM) = make_float2(av.x - v.x, av.y - v.y);
                *(float2*)(orow + 3*DIM) = make_float2(av.x * v.x, av.y * v.y);
            }
        }
}

// ---------------- fp16 split (+ hi transpose) of fp32 input -----------------
__global__ __launch_bounds__(256)
void conv_split_T(const float* __restrict__ X,
                  __half* __restrict__ Xh,  __half* __restrict__ Xl,
                  __half* __restrict__ XTh, int R, int C)
{
    __shared__ __half sh[64][65];
    int z = blockIdx.z, r0 = blockIdx.y * 64, c0 = blockIdx.x * 64;
    #pragma unroll
    for (int it = 0; it < 16; it++) {
        int idx = threadIdx.x + it * 256;
        int i = idx >> 6, j = idx & 63;
        float v = X[((size_t)z * R + r0 + i) * C + c0 + j];
        __half h = __float2half_rn(v);
        __half l = __float2half_rn(v - __half2float(h));
        Xh[((size_t)z * R + r0 + i) * C + c0 + j] = h;
        Xl[((size_t)z * R + r0 + i) * C + c0 + j] = l;
        sh[i][j] = h;
    }
    __syncthreads();
    #pragma unroll
    for (int it = 0; it < 16; it++) {
        int idx = threadIdx.x + it * 256;
        int j = idx >> 6, i = idx & 63;
        XTh[((size_t)z * C + c0 + j) * R + r0 + i] = sh[i][j];
    }
}

// ---------------------------------------------------------------------------
extern "C" void kernel_launch(void* const* d_in, const int* in_sizes, int n_in,
                              void* d_out, int out_size)
{
    const float* a_bar = (const float*)d_in[0];
    const float* b_bar = (const float*)d_in[1];
    float* out = (float*)d_out;
    float* m_a = out;
    float* m_b = out + (size_t)NB * LA * OUTC;

    __half *ah, *al, *bh, *bl, *aTh, *bTh;
    float *pe, *prm, *pri, *pcm, *pci;
    cudaGetSymbolAddress((void**)&ah,  g_ah);   cudaGetSymbolAddress((void**)&al,  g_al);
    cudaGetSymbolAddress((void**)&bh,  g_bh);   cudaGetSymbolAddress((void**)&bl,  g_bl);
    cudaGetSymbolAddress((void**)&aTh, g_aTh);  cudaGetSymbolAddress((void**)&bTh, g_bTh);
    cudaGetSymbolAddress((void**)&pe,  g_e);
    cudaGetSymbolAddress((void**)&prm, g_rowm); cudaGetSymbolAddress((void**)&pri, g_rowi);
    cudaGetSymbolAddress((void**)&pcm, g_colm); cudaGetSymbolAddress((void**)&pci, g_coli);

    cudaFuncSetAttribute(gemm1_k, cudaFuncAttributeMaxDynamicSharedMemorySize, G1_SMEM);
    cudaFuncSetAttribute(gemm_pv<false>, cudaFuncAttributeMaxDynamicSharedMemorySize, PV_SMEM);
    cudaFuncSetAttribute(gemm_pv<true>,  cudaFuncAttributeMaxDynamicSharedMemorySize, PV_SMEM);

    // 1) fp16 split + transposed hi copies of inputs
    conv_split_T<<<dim3(DIM/64, LA/64, NB), 256>>>(a_bar, ah, al, aTh, LA, DIM);
    conv_split_T<<<dim3(DIM/64, LB/64, NB), 256>>>(b_bar, bh, bl, bTh, LB, DIM);

    // 2) e = a @ b^T + on-chip row/col partial softmax stats
    gemm1_k<<<dim3(LB/128, LA/128, NB), 256, G1_SMEM>>>(ah, al, bh, bl, pe);

    // 3) reduce partials -> rowmax/rowinv, colmax/colinv
    reduce_stats_k<<<dim3(NROW/256, 2), 256>>>();

    // 4) m_a: a_tilde = softmax_row(e) @ b   (single-pass fp16)
    gemm_pv<false><<<dim3(DIM/128, LA/128, NB), 256, PV_SMEM>>>(
        pe, prm, pri, bTh, a_bar, m_a);

    // 5) m_b: b_tilde = softmax_col(e)^T @ a (single-pass fp16)
    gemm_pv<true><<<dim3(DIM/128, LB/128, NB), 256, PV_SMEM>>>(
        pe, pcm, pci, aTh, b_bar, m_b);
}